// round 2
// baseline (speedup 1.0000x reference)
#include <cuda_runtime.h>
#include <cuda_bf16.h>
#include <math_constants.h>

#define D      32000
#define D4     8000           // D / 4 (float4 count)
#define NROWS  4096
#define TA     256            // threads per CTA (one CTA per row)
#define NW     (TA / 32)
#define K      16             // per-thread private candidate capacity
#define PSTR   17             // padded stride for private smem slots (bank-conflict free-ish)
#define SCAP   2048           // compact candidate capacity in smem
#define CHI    0.005590169943749474f   // (1/32000)^0.5, double-folded like reference

__device__ float g_loss[NROWS];

__device__ __forceinline__ float warp_sum(float v) {
    #pragma unroll
    for (int o = 16; o; o >>= 1) v += __shfl_xor_sync(0xffffffffu, v, o);
    return v;
}
__device__ __forceinline__ float warp_max(float v) {
    #pragma unroll
    for (int o = 16; o; o >>= 1) v = fmaxf(v, __shfl_xor_sync(0xffffffffu, v, o));
    return v;
}

// ============================================================================
// Fused kernel: one CTA per row. max -> compact -> warp0 bisection -> loss
// ============================================================================
__global__ void __launch_bounds__(TA) fused_kernel(const float* __restrict__ X,
                                                   const int*   __restrict__ target)
{
    __shared__ float s_priv[TA * PSTR];   // ~17.4 KB private candidate slots
    __shared__ float s_cand[SCAP];        // 8 KB compact candidates
    __shared__ float s_red[NW];
    __shared__ int   s_wcnt[NW];
    __shared__ int   s_woff[NW + 1];
    __shared__ int   s_flag;
    __shared__ float s_bcast;

    const int row  = blockIdx.x;
    const int tid  = threadIdx.x;
    const int lane = tid & 31;
    const int wid  = tid >> 5;

    if (tid == 0) s_flag = 0;

    const float4* __restrict__ Xr4 = reinterpret_cast<const float4*>(X + (size_t)row * D);

    // ---- pass 1: row max (original scale; halving is exact & monotone) ----
    float lmax = -CUDART_INF_F;
    #pragma unroll 4
    for (int i = tid; i < D4; i += TA) {
        float4 v = Xr4[i];
        lmax = fmaxf(lmax, fmaxf(fmaxf(v.x, v.y), fmaxf(v.z, v.w)));
    }
    lmax = warp_max(lmax);
    if (lane == 0) s_red[wid] = lmax;
    __syncthreads();
    if (tid < 32) {
        float v = (lane < NW) ? s_red[lane] : -CUDART_INF_F;
        v = warp_max(v);
        if (lane == 0) s_bcast = v;
    }
    __syncthreads();
    const float rmax   = 0.5f * s_bcast;   // max of Xa = 0.5 * max of X (exact)
    const float thresh = rmax - 1.0f;      // tau_lo0; elements <= thresh contribute 0 always

    // ---- pass 2: re-read row (L2-resident), private compaction ----
    int k = 0;
    float* mine = s_priv + tid * PSTR;
    #pragma unroll 2
    for (int i = tid; i < D4; i += TA) {
        float4 v = Xr4[i];
        float a;
        a = 0.5f * v.x; if (a > thresh) { if (k < K) mine[k] = a; k++; }
        a = 0.5f * v.y; if (a > thresh) { if (k < K) mine[k] = a; k++; }
        a = 0.5f * v.z; if (a > thresh) { if (k < K) mine[k] = a; k++; }
        a = 0.5f * v.w; if (a > thresh) { if (k < K) mine[k] = a; k++; }
    }
    if (k > K) s_flag = 1;                 // benign race: everyone writes 1

    // ---- deterministic block prefix-sum of counts, compact to s_cand ----
    int inc = k;
    #pragma unroll
    for (int o = 1; o < 32; o <<= 1) {
        int n = __shfl_up_sync(0xffffffffu, inc, o);
        if (lane >= o) inc += n;
    }
    if (lane == 31) s_wcnt[wid] = inc;
    __syncthreads();
    if (tid == 0) {
        int a = 0;
        #pragma unroll
        for (int w = 0; w < NW; w++) { s_woff[w] = a; a += s_wcnt[w]; }
        s_woff[NW] = a;
    }
    __syncthreads();
    const int  total = s_woff[NW];
    const bool fb_pre = (total > SCAP);
    if (!fb_pre) {
        int off = s_woff[wid] + inc - k;   // exclusive prefix
        int kk = (k < K) ? k : K;
        for (int j = 0; j < kk; j++) s_cand[off + j] = mine[j];
    }
    float xt = 0.f;
    if (tid == 0) xt = X[(size_t)row * D + target[row]];   // thread 0 == warp0 lane0
    __syncthreads();

    const bool fb = (s_flag != 0) || fb_pre;   // fallback: stream full row

    if (wid != 0) return;   // only warp 0 continues

    // ---- warp-synchronous bisection (identical math to reference) ----
    const float* __restrict__ Xr = X + (size_t)row * D;
    const int count = total;

    auto feval = [&](float tau) -> float {
        float acc = 0.f;
        if (!fb) {
            #pragma unroll 4
            for (int i = lane; i < count; i += 32) {
                float t = fmaxf(s_cand[i] - tau, 0.f);
                acc = fmaf(t, t, acc);
            }
        } else {
            for (int i = lane; i < D; i += 32) {
                float t = fmaxf(0.5f * Xr[i] - tau, 0.f);
                acc = fmaf(t, t, acc);
            }
        }
        return warp_sum(acc);
    };

    float tau_lo = rmax - 1.0f;
    const float tau_hi = rmax - CHI;

    const float f_lo = feval(tau_lo) - 1.0f;   // computed ONCE (matches reference closure)
    float dm = tau_hi - tau_lo;
    float tau_m = tau_lo;
    #pragma unroll 1
    for (int it = 0; it < 50; it++) {
        dm *= 0.5f;
        tau_m = tau_lo + dm;
        float f_m = feval(tau_m) - 1.0f;
        if (f_m * f_lo >= 0.f) tau_lo = tau_m;
    }

    // ---- final stats at tau_m ----
    // p_raw = t^2, S = sum p_raw, sum p^1.5 = sum t^3 / S^1.5, sum p*X = 2*sum(p_raw*Xa)/S
    float S = 0.f, A15 = 0.f, PX = 0.f;
    if (!fb) {
        #pragma unroll 4
        for (int i = lane; i < count; i += 32) {
            float v = s_cand[i];
            float t = fmaxf(v - tau_m, 0.f);
            float pr = t * t;
            S += pr; A15 = fmaf(pr, t, A15); PX = fmaf(pr, v, PX);
        }
    } else {
        for (int i = lane; i < D; i += 32) {
            float v = 0.5f * Xr[i];
            float t = fmaxf(v - tau_m, 0.f);
            float pr = t * t;
            S += pr; A15 = fmaf(pr, t, A15); PX = fmaf(pr, v, PX);
        }
    }
    S = warp_sum(S); A15 = warp_sum(A15); PX = warp_sum(PX);

    float sum_p15 = A15 / (S * sqrtf(S));
    float omega   = (1.0f - sum_p15) / 0.75f;     // alpha*(alpha-1) = 0.75
    float loss    = omega + 2.0f * PX / S - xt;

    if (lane == 0) g_loss[row] = loss;
}

// ============================================================================
// Deterministic mean over rows
// ============================================================================
__global__ void __launch_bounds__(1024) reduce_kernel(float* __restrict__ out)
{
    __shared__ float s[1024];
    float a = 0.f;
    for (int i = threadIdx.x; i < NROWS; i += 1024) a += g_loss[i];
    s[threadIdx.x] = a;
    __syncthreads();
    #pragma unroll
    for (int o = 512; o; o >>= 1) {
        if (threadIdx.x < o) s[threadIdx.x] += s[threadIdx.x + o];
        __syncthreads();
    }
    if (threadIdx.x == 0) out[0] = s[0] / (float)NROWS;
}

// ============================================================================
extern "C" void kernel_launch(void* const* d_in, const int* in_sizes, int n_in,
                              void* d_out, int out_size)
{
    const float* X      = (const float*)d_in[0];
    const int*   target = (const int*)  d_in[1];
    float*       out    = (float*)d_out;

    fused_kernel<<<NROWS, TA>>>(X, target);
    reduce_kernel<<<1, 1024>>>(out);
}

// round 3
// speedup vs baseline: 5.8652x; 5.8652x over previous
#include <cuda_runtime.h>
#include <cuda_bf16.h>
#include <math_constants.h>

#define D       32000
#define D4      8000            // D/4 float4s
#define NROWS   4096
#define TA      256
#define NWARP   8
#define CHUNK4  1000            // float4s per warp (contiguous chunk)
#define WCAP    1024            // per-warp candidate capacity
#define CHI     0.005590169943749474f   // (1/32000)^0.5 (double-folded like reference)

__device__ float g_loss[NROWS];

__device__ __forceinline__ float warp_sum(float v) {
    #pragma unroll
    for (int o = 16; o; o >>= 1) v += __shfl_xor_sync(0xffffffffu, v, o);
    return v;
}
__device__ __forceinline__ float warp_max(float v) {
    #pragma unroll
    for (int o = 16; o; o >>= 1) v = fmaxf(v, __shfl_xor_sync(0xffffffffu, v, o));
    return v;
}

// ============================================================================
// Fused kernel: one CTA (8 warps) per row.
// pass1 max -> per-warp ballot compaction -> all-warp bisection -> loss
// ============================================================================
__global__ void __launch_bounds__(TA) fused_kernel(const float* __restrict__ X,
                                                   const int*   __restrict__ target)
{
    __shared__ float s_buf[NWARP][WCAP];   // 32 KB candidate buffers (Xa scale)
    __shared__ float s_part[2][NWARP];     // double-buffered feval partials
    __shared__ float s_p3[3][NWARP];       // final-stat partials
    __shared__ float s_max[NWARP];
    __shared__ int   s_cnt[NWARP];
    __shared__ int   s_fb;

    const int row  = blockIdx.x;
    const int tid  = threadIdx.x;
    const int lane = tid & 31;
    const int wid  = tid >> 5;

    if (tid == 0) s_fb = 0;

    const float4* __restrict__ Xr4 = reinterpret_cast<const float4*>(X + (size_t)row * D);
    const float*  __restrict__ Xr  = X + (size_t)row * D;

    float xt = 0.f;
    if (tid == 0) xt = Xr[target[row]];    // early LDG; thread 0 writes the loss later

    // ---- pass 1: row max on X scale (coalesced, block-wide) ----
    float lmax = -CUDART_INF_F;
    #pragma unroll 4
    for (int i = tid; i < D4; i += TA) {
        float4 v = Xr4[i];
        lmax = fmaxf(lmax, fmaxf(fmaxf(v.x, v.y), fmaxf(v.z, v.w)));
    }
    lmax = warp_max(lmax);
    if (lane == 0) s_max[wid] = lmax;
    __syncthreads();
    float rmaxX = s_max[0];
    #pragma unroll
    for (int w = 1; w < NWARP; w++) rmaxX = fmaxf(rmaxX, s_max[w]);   // every thread, same result

    const float rmax    = 0.5f * rmaxX;                 // exact
    const float threshX = rmaxX - 2.0f - 1e-5f;         // X-scale filter with margin
                                                        // (below-threshold elems contribute ~0)

    // ---- pass 2: per-warp ballot compaction over contiguous chunk ----
    {
        const float4* __restrict__ W4 = Xr4 + wid * CHUNK4;
        int k = 0;
        for (int j = 0; j < 32; j++) {                  // 32*32 = 1024 >= CHUNK4
            int  fi  = lane + 32 * j;
            bool inb = fi < CHUNK4;
            float4 v = inb ? W4[fi] : make_float4(-1e30f, -1e30f, -1e30f, -1e30f);
            float comp[4] = {v.x, v.y, v.z, v.w};
            #pragma unroll
            for (int c = 0; c < 4; c++) {
                float a = comp[c];
                bool pred = a > threshX;                // inb handled by -1e30 fill
                unsigned m = __ballot_sync(0xffffffffu, pred);
                if (pred) {
                    int pos = k + __popc(m & ((1u << lane) - 1u));
                    if (pos < WCAP) s_buf[wid][pos] = 0.5f * a;   // store on Xa scale
                }
                k += __popc(m);
            }
        }
        if (k > WCAP) s_fb = 1;                         // benign race (all write 1)
        if (lane == 0) s_cnt[wid] = (k < WCAP) ? k : WCAP;
    }
    __syncthreads();

    const bool fb  = (s_fb != 0);                       // ~never (needs >8192 candidates)
    const int  cnt = s_cnt[wid];

    // ---- per-warp partial f(tau) ----
    auto fpart = [&](float tau) -> float {
        float acc = 0.f;
        if (!fb) {
            #pragma unroll 4
            for (int i = lane; i < cnt; i += 32) {
                float t = fmaxf(s_buf[wid][i] - tau, 0.f);
                acc = fmaf(t, t, acc);
            }
        } else {
            // block-wide coalesced full-row stream; this warp's partial
            for (int i = tid; i < D; i += TA) {
                float t = fmaxf(0.5f * Xr[i] - tau, 0.f);
                acc = fmaf(t, t, acc);
            }
        }
        return warp_sum(acc);
    };

    float tau_lo = rmax - 1.0f;
    const float tau_hi = rmax - CHI;

    // f_lo computed ONCE (matches reference closure)
    {
        float p = fpart(tau_lo);
        if (lane == 0) s_part[0][wid] = p;
    }
    __syncthreads();
    float f_lo = -1.0f;
    #pragma unroll
    for (int w = 0; w < NWARP; w++) f_lo += s_part[0][w];
    __syncthreads();

    float dm = tau_hi - tau_lo;
    float tau_m = tau_lo;
    #pragma unroll 1
    for (int it = 0; it < 50; it++) {
        dm *= 0.5f;
        tau_m = tau_lo + dm;
        float p = fpart(tau_m);
        int b = it & 1;
        if (lane == 0) s_part[b][wid] = p;
        __syncthreads();
        float f_m = -1.0f;
        #pragma unroll
        for (int w = 0; w < NWARP; w++) f_m += s_part[b][w];
        if (f_m * f_lo >= 0.f) tau_lo = tau_m;          // every thread: identical update
    }

    // ---- final stats at tau_m ----
    // p_raw=t^2, S=sum p_raw, sum p^1.5 = sum t^3 / S^1.5, sum p*X = 2*sum(p_raw*Xa)/S
    float S = 0.f, A15 = 0.f, PX = 0.f;
    if (!fb) {
        #pragma unroll 4
        for (int i = lane; i < cnt; i += 32) {
            float v = s_buf[wid][i];
            float t = fmaxf(v - tau_m, 0.f);
            float pr = t * t;
            S += pr; A15 = fmaf(pr, t, A15); PX = fmaf(pr, v, PX);
        }
    } else {
        for (int i = tid; i < D; i += TA) {
            float v = 0.5f * Xr[i];
            float t = fmaxf(v - tau_m, 0.f);
            float pr = t * t;
            S += pr; A15 = fmaf(pr, t, A15); PX = fmaf(pr, v, PX);
        }
    }
    S = warp_sum(S); A15 = warp_sum(A15); PX = warp_sum(PX);
    if (lane == 0) { s_p3[0][wid] = S; s_p3[1][wid] = A15; s_p3[2][wid] = PX; }
    __syncthreads();

    if (tid == 0) {
        float St = 0.f, At = 0.f, Pt = 0.f;
        #pragma unroll
        for (int w = 0; w < NWARP; w++) { St += s_p3[0][w]; At += s_p3[1][w]; Pt += s_p3[2][w]; }
        float sum_p15 = At / (St * sqrtf(St));
        float omega   = (1.0f - sum_p15) / 0.75f;       // alpha*(alpha-1) = 0.75
        float loss    = omega + 2.0f * Pt / St - xt;
        g_loss[row] = loss;
    }
}

// ============================================================================
// Deterministic mean over rows
// ============================================================================
__global__ void __launch_bounds__(1024) reduce_kernel(float* __restrict__ out)
{
    __shared__ float s[1024];
    float a = 0.f;
    for (int i = threadIdx.x; i < NROWS; i += 1024) a += g_loss[i];
    s[threadIdx.x] = a;
    __syncthreads();
    #pragma unroll
    for (int o = 512; o; o >>= 1) {
        if (threadIdx.x < o) s[threadIdx.x] += s[threadIdx.x + o];
        __syncthreads();
    }
    if (threadIdx.x == 0) out[0] = s[0] / (float)NROWS;
}

// ============================================================================
extern "C" void kernel_launch(void* const* d_in, const int* in_sizes, int n_in,
                              void* d_out, int out_size)
{
    const float* X      = (const float*)d_in[0];
    const int*   target = (const int*)  d_in[1];
    float*       out    = (float*)d_out;

    fused_kernel<<<NROWS, TA>>>(X, target);
    reduce_kernel<<<1, 1024>>>(out);
}